// round 12
// baseline (speedup 1.0000x reference)
#include <cuda_runtime.h>
#include <cuda_fp16.h>

#define EPS 1e-4f
#define NDIM 512
#define H2S 131072   // half2 per sample

__device__ __half2 g_half[128 * (size_t)H2S];   // 64 MB fp16 working copy

__device__ __forceinline__ float4 z4f() { return make_float4(0.f, 0.f, 0.f, 0.f); }
__device__ __forceinline__ float2 h2f(unsigned u) {
    __half2 h = *reinterpret_cast<__half2*>(&u);
    return __half22float2(h);
}
__device__ __forceinline__ float2 pack_h4(float4 v) {
    __half2 h0 = __floats2half2_rn(v.x, v.y);
    __half2 h1 = __floats2half2_rn(v.z, v.w);
    float2 r;
    r.x = __uint_as_float(*reinterpret_cast<unsigned*>(&h0));
    r.y = __uint_as_float(*reinterpret_cast<unsigned*>(&h1));
    return r;
}

__global__ __launch_bounds__(1024, 1)
void sinkhorn_kernel(const float* __restrict__ s,
                     const int* __restrict__ nrows,
                     float* __restrict__ out) {
    extern __shared__ __align__(16) float red[];        // 32*512 floats = 64 KB
    __shared__ __align__(16) float c_sh[NDIM];
    __shared__ float ssumA[32];
    __shared__ float ssumB[32];

    const int b    = blockIdx.x;
    const int tid  = threadIdx.x;
    const int lane = tid & 31;
    const int wid  = tid >> 5;
    const int n    = nrows[b];
    const bool g2  = (n > 256);
    const float* __restrict__ S = s   + (size_t)b * (NDIM * NDIM);
    float* __restrict__       O = out + (size_t)b * (NDIM * NDIM);
    __half2* __restrict__     H = g_half + (size_t)b * H2S;
    const float4* __restrict__ c4s = (const float4*)c_sh;

    // ========== pass 0: column sums (r = 1) + fp16 conversion of active rows ====
    {
        const int j4    = (tid & 127) << 2;
        const int slice = tid >> 7;                      // 0..7
        const int jh    = j4 >> 1;                       // half2 col index
        float4 a0 = z4f(), a1 = z4f(), a2 = z4f(), a3 = z4f();
        if (j4 < n) {
            int i = slice;
            for (; i + 24 < n; i += 32) {
                float4 v0 = __ldcs((const float4*)(S + (size_t)(i)      * NDIM + j4));
                float4 v1 = __ldcs((const float4*)(S + (size_t)(i + 8)  * NDIM + j4));
                float4 v2 = __ldcs((const float4*)(S + (size_t)(i + 16) * NDIM + j4));
                float4 v3 = __ldcs((const float4*)(S + (size_t)(i + 24) * NDIM + j4));
                a0.x += v0.x; a0.y += v0.y; a0.z += v0.z; a0.w += v0.w;
                a1.x += v1.x; a1.y += v1.y; a1.z += v1.z; a1.w += v1.w;
                a2.x += v2.x; a2.y += v2.y; a2.z += v2.z; a2.w += v2.w;
                a3.x += v3.x; a3.y += v3.y; a3.z += v3.z; a3.w += v3.w;
                *(float2*)(H + (size_t)(i)      * (NDIM/2) + jh) = pack_h4(v0);
                *(float2*)(H + (size_t)(i + 8)  * (NDIM/2) + jh) = pack_h4(v1);
                *(float2*)(H + (size_t)(i + 16) * (NDIM/2) + jh) = pack_h4(v2);
                *(float2*)(H + (size_t)(i + 24) * (NDIM/2) + jh) = pack_h4(v3);
            }
            for (; i < n; i += 8) {
                float4 v0 = __ldcs((const float4*)(S + (size_t)i * NDIM + j4));
                a0.x += v0.x; a0.y += v0.y; a0.z += v0.z; a0.w += v0.w;
                *(float2*)(H + (size_t)i * (NDIM/2) + jh) = pack_h4(v0);
            }
            a0.x += a1.x + a2.x + a3.x; a0.y += a1.y + a2.y + a3.y;
            a0.z += a1.z + a2.z + a3.z; a0.w += a1.w + a2.w + a3.w;
        }
        *(float4*)(red + slice * NDIM + j4) = a0;
        __syncthreads();

        float cv = 0.0f;
        if (tid < n) {
            float cs = 0.0f;
            #pragma unroll
            for (int ss = 0; ss < 8; ++ss) cs += red[ss * NDIM + tid];
            cv = __fdividef(1.0f, cs + EPS * (float)n);
        }
        if (tid < NDIM) c_sh[tid] = cv;
        float v = cv;
        #pragma unroll
        for (int o = 16; o; o >>= 1) v += __shfl_xor_sync(0xffffffffu, v, o);
        if (lane == 0) ssumB[wid] = v;
        __syncthreads();
    }
    float sum_c = 0.0f;
    #pragma unroll
    for (int k = 0; k < 32; ++k) sum_c += ssumB[k];

    // ==== 4 fused passes: row(2f+1) + col(2f+2), pipeline + c-in-registers ======
    #pragma unroll 1
    for (int f = 0; f < 4; ++f) {
        const float eps_c = EPS * sum_c;
        float4 acc0 = z4f(), acc1 = z4f(), acc2 = z4f(), acc3 = z4f();
        float rpart = 0.0f;
        const uint4 uz = make_uint4(0u, 0u, 0u, 0u);

        // c held in registers for the whole pass (constant across rows)
        const float4 c0 = c4s[lane * 2],      c1 = c4s[lane * 2 + 1];
        const float4 c2 = c4s[64 + lane * 2], c3 = c4s[64 + lane * 2 + 1];

        int i = wid;
        uint4 u0 = uz, u1 = uz;
        if (i < n) {
            const uint4* __restrict__ rowH = (const uint4*)(H + (size_t)i * (NDIM/2));
            u0 = rowH[lane];
            if (g2) u1 = rowH[lane + 32];
        }
        #pragma unroll 1
        while (i < n) {
            const int inx = i + 32;
            uint4 n0 = uz, n1 = uz;
            if (inx < n) {                               // prefetch next row first
                const uint4* __restrict__ rowN = (const uint4*)(H + (size_t)inx * (NDIM/2));
                n0 = rowN[lane];
                if (g2) n1 = rowN[lane + 32];
            }

            float t;
            {
                float2 f0 = h2f(u0.x), f1 = h2f(u0.y), f2 = h2f(u0.z), f3 = h2f(u0.w);
                float2 f4 = h2f(u1.x), f5 = h2f(u1.y), f6 = h2f(u1.z), f7 = h2f(u1.w);
                float d0 = 0.f, d1 = 0.f, d2 = 0.f, d3 = 0.f;
                d0 = fmaf(f0.x, c0.x, d0); d1 = fmaf(f0.y, c0.y, d1);
                d2 = fmaf(f1.x, c0.z, d2); d3 = fmaf(f1.y, c0.w, d3);
                d0 = fmaf(f2.x, c1.x, d0); d1 = fmaf(f2.y, c1.y, d1);
                d2 = fmaf(f3.x, c1.z, d2); d3 = fmaf(f3.y, c1.w, d3);
                d0 = fmaf(f4.x, c2.x, d0); d1 = fmaf(f4.y, c2.y, d1);
                d2 = fmaf(f5.x, c2.z, d2); d3 = fmaf(f5.y, c2.w, d3);
                d0 = fmaf(f6.x, c3.x, d0); d1 = fmaf(f6.y, c3.y, d1);
                d2 = fmaf(f7.x, c3.z, d2); d3 = fmaf(f7.y, c3.w, d3);
                t = (d0 + d1) + (d2 + d3);
            }
            #pragma unroll
            for (int o = 16; o; o >>= 1) t += __shfl_xor_sync(0xffffffffu, t, o);
            const float ri = __fdividef(1.0f, t + eps_c);
            rpart += ri;

            {
                float2 f0 = h2f(u0.x), f1 = h2f(u0.y), f2 = h2f(u0.z), f3 = h2f(u0.w);
                acc0.x = fmaf(ri, f0.x, acc0.x); acc0.y = fmaf(ri, f0.y, acc0.y);
                acc0.z = fmaf(ri, f1.x, acc0.z); acc0.w = fmaf(ri, f1.y, acc0.w);
                acc1.x = fmaf(ri, f2.x, acc1.x); acc1.y = fmaf(ri, f2.y, acc1.y);
                acc1.z = fmaf(ri, f3.x, acc1.z); acc1.w = fmaf(ri, f3.y, acc1.w);
            }
            {
                float2 f4 = h2f(u1.x), f5 = h2f(u1.y), f6 = h2f(u1.z), f7 = h2f(u1.w);
                acc2.x = fmaf(ri, f4.x, acc2.x); acc2.y = fmaf(ri, f4.y, acc2.y);
                acc2.z = fmaf(ri, f5.x, acc2.z); acc2.w = fmaf(ri, f5.y, acc2.w);
                acc3.x = fmaf(ri, f6.x, acc3.x); acc3.y = fmaf(ri, f6.y, acc3.y);
                acc3.z = fmaf(ri, f7.x, acc3.z); acc3.w = fmaf(ri, f7.y, acc3.w);
            }
            u0 = n0; u1 = n1; i = inx;
        }

        float4* __restrict__ rw = (float4*)(red + wid * NDIM);
        rw[lane * 2]          = acc0;
        rw[lane * 2 + 1]      = acc1;
        rw[64 + lane * 2]     = acc2;
        rw[64 + lane * 2 + 1] = acc3;
        if (lane == 0) ssumA[wid] = rpart;   // warp-uniform
        __syncthreads();

        float sum_r = 0.0f;
        #pragma unroll
        for (int k = 0; k < 32; ++k) sum_r += ssumA[k];

        float cv = 0.0f;
        if (tid < n) {
            float cs = 0.0f;
            #pragma unroll
            for (int w = 0; w < 32; ++w) cs += red[w * NDIM + tid];
            cv = __fdividef(1.0f, cs + EPS * sum_r);
        }
        if (tid < NDIM) c_sh[tid] = cv;
        float v = cv;
        #pragma unroll
        for (int o = 16; o; o >>= 1) v += __shfl_xor_sync(0xffffffffu, v, o);
        if (lane == 0) ssumB[wid] = v;
        __syncthreads();
        sum_c = 0.0f;
        #pragma unroll
        for (int k = 0; k < 32; ++k) sum_c += ssumB[k];
    }

    // ====== final pass: row step (iter 9) on the fp16 copy, fused output write ==
    {
        const float eps_c = EPS * sum_c;
        const uint4 uz = make_uint4(0u, 0u, 0u, 0u);
        const float4 c0 = c4s[lane * 2],      c1 = c4s[lane * 2 + 1];
        const float4 c2 = c4s[64 + lane * 2], c3 = c4s[64 + lane * 2 + 1];
        for (int i = wid; i < n; i += 32) {
            const uint4* __restrict__ rowH = (const uint4*)(H + (size_t)i * (NDIM/2));
            float4* __restrict__ orow = (float4*)(O + (size_t)i * NDIM);
            uint4 u0 = __ldcs(rowH + lane);
            uint4 u1 = uz;
            if (g2) u1 = __ldcs(rowH + lane + 32);

            float2 f0 = h2f(u0.x), f1 = h2f(u0.y), f2 = h2f(u0.z), f3 = h2f(u0.w);
            float2 f4 = h2f(u1.x), f5 = h2f(u1.y), f6 = h2f(u1.z), f7 = h2f(u1.w);
            float d0 = 0.f, d1 = 0.f, d2 = 0.f, d3 = 0.f;
            d0 = fmaf(f0.x, c0.x, d0); d1 = fmaf(f0.y, c0.y, d1);
            d2 = fmaf(f1.x, c0.z, d2); d3 = fmaf(f1.y, c0.w, d3);
            d0 = fmaf(f2.x, c1.x, d0); d1 = fmaf(f2.y, c1.y, d1);
            d2 = fmaf(f3.x, c1.z, d2); d3 = fmaf(f3.y, c1.w, d3);
            d0 = fmaf(f4.x, c2.x, d0); d1 = fmaf(f4.y, c2.y, d1);
            d2 = fmaf(f5.x, c2.z, d2); d3 = fmaf(f5.y, c2.w, d3);
            d0 = fmaf(f6.x, c3.x, d0); d1 = fmaf(f6.y, c3.y, d1);
            d2 = fmaf(f7.x, c3.z, d2); d3 = fmaf(f7.y, c3.w, d3);
            float t = (d0 + d1) + (d2 + d3);
            #pragma unroll
            for (int o = 16; o; o >>= 1) t += __shfl_xor_sync(0xffffffffu, t, o);
            const float ri = __fdividef(1.0f, t + eps_c);

            float4 w;
            w.x = (f0.x + EPS) * ri * c0.x; w.y = (f0.y + EPS) * ri * c0.y;
            w.z = (f1.x + EPS) * ri * c0.z; w.w = (f1.y + EPS) * ri * c0.w;
            __stcs(orow + lane * 2, w);
            w.x = (f2.x + EPS) * ri * c1.x; w.y = (f2.y + EPS) * ri * c1.y;
            w.z = (f3.x + EPS) * ri * c1.z; w.w = (f3.y + EPS) * ri * c1.w;
            __stcs(orow + lane * 2 + 1, w);
            w.x = (f4.x + EPS) * ri * c2.x; w.y = (f4.y + EPS) * ri * c2.y;
            w.z = (f5.x + EPS) * ri * c2.z; w.w = (f5.y + EPS) * ri * c2.w;
            __stcs(orow + 64 + lane * 2, w);
            w.x = (f6.x + EPS) * ri * c3.x; w.y = (f6.y + EPS) * ri * c3.y;
            w.z = (f7.x + EPS) * ri * c3.z; w.w = (f7.y + EPS) * ri * c3.w;
            __stcs(orow + 64 + lane * 2 + 1, w);
        }
        // zero-fill rows i >= n
        float4* __restrict__ O4 = (float4*)O;
        const float4 z = z4f();
        for (int idx = n * 128 + tid; idx < NDIM * 128; idx += 1024)
            __stcs(O4 + idx, z);
    }
}

extern "C" void kernel_launch(void* const* d_in, const int* in_sizes, int n_in,
                              void* d_out, int out_size) {
    const float* s     = (const float*)d_in[0];
    const int*   nrows = (const int*)d_in[1];
    float*       out   = (float*)d_out;
    const int B = in_sizes[1];
    const int shbytes = 32 * NDIM * sizeof(float);   // 64 KB dynamic
    static bool attr_set = false;
    if (!attr_set) {
        cudaFuncSetAttribute(sinkhorn_kernel,
                             cudaFuncAttributeMaxDynamicSharedMemorySize, shbytes);
        attr_set = true;
    }
    sinkhorn_kernel<<<B, 1024, shbytes>>>(s, nrows, out);
}

// round 13
// speedup vs baseline: 1.0227x; 1.0227x over previous
#include <cuda_runtime.h>
#include <cuda_fp16.h>

#define EPS 1e-4f
#define NDIM 512
#define H2S 131072   // half2 per sample

__device__ __half2 g_half[128 * (size_t)H2S];   // 64 MB fp16 working copy

__device__ __forceinline__ float4 z4f() { return make_float4(0.f, 0.f, 0.f, 0.f); }
__device__ __forceinline__ float2 h2f(unsigned u) {
    __half2 h = *reinterpret_cast<__half2*>(&u);
    return __half22float2(h);
}
__device__ __forceinline__ float2 pack_h4(float4 v) {
    __half2 h0 = __floats2half2_rn(v.x, v.y);
    __half2 h1 = __floats2half2_rn(v.z, v.w);
    float2 r;
    r.x = __uint_as_float(*reinterpret_cast<unsigned*>(&h0));
    r.y = __uint_as_float(*reinterpret_cast<unsigned*>(&h1));
    return r;
}

__global__ __launch_bounds__(1024, 1)
void sinkhorn_kernel(const float* __restrict__ s,
                     const int* __restrict__ nrows,
                     float* __restrict__ out) {
    extern __shared__ __align__(16) float red[];        // 32*512 floats = 64 KB
    __shared__ __align__(16) float c_sh[NDIM];
    __shared__ float ssumA[32];
    __shared__ float ssumB[32];

    const int b    = blockIdx.x;
    const int tid  = threadIdx.x;
    const int lane = tid & 31;
    const int wid  = tid >> 5;
    const int n    = nrows[b];
    const bool g2  = (n > 256);
    const float* __restrict__ S = s   + (size_t)b * (NDIM * NDIM);
    float* __restrict__       O = out + (size_t)b * (NDIM * NDIM);
    __half2* __restrict__     H = g_half + (size_t)b * H2S;
    const float4* __restrict__ c4s = (const float4*)c_sh;

    // ========== pass 0: column sums (r = 1) + fp16 conversion of active rows ====
    {
        const int j4    = (tid & 127) << 2;
        const int slice = tid >> 7;                      // 0..7
        const int jh    = j4 >> 1;                       // half2 col index
        float4 a0 = z4f(), a1 = z4f(), a2 = z4f(), a3 = z4f();
        if (j4 < n) {
            int i = slice;
            for (; i + 24 < n; i += 32) {
                float4 v0 = __ldcs((const float4*)(S + (size_t)(i)      * NDIM + j4));
                float4 v1 = __ldcs((const float4*)(S + (size_t)(i + 8)  * NDIM + j4));
                float4 v2 = __ldcs((const float4*)(S + (size_t)(i + 16) * NDIM + j4));
                float4 v3 = __ldcs((const float4*)(S + (size_t)(i + 24) * NDIM + j4));
                a0.x += v0.x; a0.y += v0.y; a0.z += v0.z; a0.w += v0.w;
                a1.x += v1.x; a1.y += v1.y; a1.z += v1.z; a1.w += v1.w;
                a2.x += v2.x; a2.y += v2.y; a2.z += v2.z; a2.w += v2.w;
                a3.x += v3.x; a3.y += v3.y; a3.z += v3.z; a3.w += v3.w;
                *(float2*)(H + (size_t)(i)      * (NDIM/2) + jh) = pack_h4(v0);
                *(float2*)(H + (size_t)(i + 8)  * (NDIM/2) + jh) = pack_h4(v1);
                *(float2*)(H + (size_t)(i + 16) * (NDIM/2) + jh) = pack_h4(v2);
                *(float2*)(H + (size_t)(i + 24) * (NDIM/2) + jh) = pack_h4(v3);
            }
            for (; i < n; i += 8) {
                float4 v0 = __ldcs((const float4*)(S + (size_t)i * NDIM + j4));
                a0.x += v0.x; a0.y += v0.y; a0.z += v0.z; a0.w += v0.w;
                *(float2*)(H + (size_t)i * (NDIM/2) + jh) = pack_h4(v0);
            }
            a0.x += a1.x + a2.x + a3.x; a0.y += a1.y + a2.y + a3.y;
            a0.z += a1.z + a2.z + a3.z; a0.w += a1.w + a2.w + a3.w;
        }
        *(float4*)(red + slice * NDIM + j4) = a0;
        __syncthreads();

        float cv = 0.0f;
        if (tid < n) {
            float cs = 0.0f;
            #pragma unroll
            for (int ss = 0; ss < 8; ++ss) cs += red[ss * NDIM + tid];
            cv = __fdividef(1.0f, cs + EPS * (float)n);
        }
        if (tid < NDIM) c_sh[tid] = cv;
        float v = cv;
        #pragma unroll
        for (int o = 16; o; o >>= 1) v += __shfl_xor_sync(0xffffffffu, v, o);
        if (lane == 0) ssumB[wid] = v;
        __syncthreads();
    }
    float sum_c = 0.0f;
    #pragma unroll
    for (int k = 0; k < 32; ++k) sum_c += ssumB[k];

    // ==== 4 fused passes: row(2f+1) + col(2f+2), one-row pipeline, c via SMEM ===
    #pragma unroll 1
    for (int f = 0; f < 4; ++f) {
        const float eps_c = EPS * sum_c;
        float4 acc0 = z4f(), acc1 = z4f(), acc2 = z4f(), acc3 = z4f();
        float rpart = 0.0f;
        const uint4 uz = make_uint4(0u, 0u, 0u, 0u);

        int i = wid;
        uint4 u0 = uz, u1 = uz;
        if (i < n) {
            const uint4* __restrict__ rowH = (const uint4*)(H + (size_t)i * (NDIM/2));
            u0 = rowH[lane];
            if (g2) u1 = rowH[lane + 32];
        }
        #pragma unroll 1
        while (i < n) {
            const int inx = i + 32;
            uint4 n0 = uz, n1 = uz;
            if (inx < n) {                               // prefetch next row first
                const uint4* __restrict__ rowN = (const uint4*)(H + (size_t)inx * (NDIM/2));
                n0 = rowN[lane];
                if (g2) n1 = rowN[lane + 32];
            }

            // dot with c from SMEM (c regs are transient — keeps pressure low)
            float t;
            {
                float4 c0 = c4s[lane * 2],      c1 = c4s[lane * 2 + 1];
                float4 c2 = c4s[64 + lane * 2], c3 = c4s[64 + lane * 2 + 1];
                float2 f0 = h2f(u0.x), f1 = h2f(u0.y), f2 = h2f(u0.z), f3 = h2f(u0.w);
                float2 f4 = h2f(u1.x), f5 = h2f(u1.y), f6 = h2f(u1.z), f7 = h2f(u1.w);
                float d0 = 0.f, d1 = 0.f, d2 = 0.f, d3 = 0.f;
                d0 = fmaf(f0.x, c0.x, d0); d1 = fmaf(f0.y, c0.y, d1);
                d2 = fmaf(f1.x, c0.z, d2); d3 = fmaf(f1.y, c0.w, d3);
                d0 = fmaf(f2.x, c1.x, d0); d1 = fmaf(f2.y, c1.y, d1);
                d2 = fmaf(f3.x, c1.z, d2); d3 = fmaf(f3.y, c1.w, d3);
                d0 = fmaf(f4.x, c2.x, d0); d1 = fmaf(f4.y, c2.y, d1);
                d2 = fmaf(f5.x, c2.z, d2); d3 = fmaf(f5.y, c2.w, d3);
                d0 = fmaf(f6.x, c3.x, d0); d1 = fmaf(f6.y, c3.y, d1);
                d2 = fmaf(f7.x, c3.z, d2); d3 = fmaf(f7.y, c3.w, d3);
                t = (d0 + d1) + (d2 + d3);
            }
            #pragma unroll
            for (int o = 16; o; o >>= 1) t += __shfl_xor_sync(0xffffffffu, t, o);
            const float ri = __fdividef(1.0f, t + eps_c);
            rpart += ri;

            {   // re-convert (cheap F2F) and accumulate column partials
                float2 f0 = h2f(u0.x), f1 = h2f(u0.y), f2 = h2f(u0.z), f3 = h2f(u0.w);
                acc0.x = fmaf(ri, f0.x, acc0.x); acc0.y = fmaf(ri, f0.y, acc0.y);
                acc0.z = fmaf(ri, f1.x, acc0.z); acc0.w = fmaf(ri, f1.y, acc0.w);
                acc1.x = fmaf(ri, f2.x, acc1.x); acc1.y = fmaf(ri, f2.y, acc1.y);
                acc1.z = fmaf(ri, f3.x, acc1.z); acc1.w = fmaf(ri, f3.y, acc1.w);
            }
            {
                float2 f4 = h2f(u1.x), f5 = h2f(u1.y), f6 = h2f(u1.z), f7 = h2f(u1.w);
                acc2.x = fmaf(ri, f4.x, acc2.x); acc2.y = fmaf(ri, f4.y, acc2.y);
                acc2.z = fmaf(ri, f5.x, acc2.z); acc2.w = fmaf(ri, f5.y, acc2.w);
                acc3.x = fmaf(ri, f6.x, acc3.x); acc3.y = fmaf(ri, f6.y, acc3.y);
                acc3.z = fmaf(ri, f7.x, acc3.z); acc3.w = fmaf(ri, f7.y, acc3.w);
            }
            u0 = n0; u1 = n1; i = inx;
        }

        float4* __restrict__ rw = (float4*)(red + wid * NDIM);
        rw[lane * 2]          = acc0;
        rw[lane * 2 + 1]      = acc1;
        rw[64 + lane * 2]     = acc2;
        rw[64 + lane * 2 + 1] = acc3;
        if (lane == 0) ssumA[wid] = rpart;   // warp-uniform
        __syncthreads();

        float sum_r = 0.0f;
        #pragma unroll
        for (int k = 0; k < 32; ++k) sum_r += ssumA[k];

        float cv = 0.0f;
        if (tid < n) {
            float cs = 0.0f;
            #pragma unroll
            for (int w = 0; w < 32; ++w) cs += red[w * NDIM + tid];
            cv = __fdividef(1.0f, cs + EPS * sum_r);
        }
        if (tid < NDIM) c_sh[tid] = cv;
        float v = cv;
        #pragma unroll
        for (int o = 16; o; o >>= 1) v += __shfl_xor_sync(0xffffffffu, v, o);
        if (lane == 0) ssumB[wid] = v;
        __syncthreads();
        sum_c = 0.0f;
        #pragma unroll
        for (int k = 0; k < 32; ++k) sum_c += ssumB[k];
    }

    // == final pass: row step (iter 9) on fp16 copy, pipelined, fused out write ==
    {
        const float eps_c = EPS * sum_c;
        const uint4 uz = make_uint4(0u, 0u, 0u, 0u);

        int i = wid;
        uint4 u0 = uz, u1 = uz;
        if (i < n) {
            const uint4* __restrict__ rowH = (const uint4*)(H + (size_t)i * (NDIM/2));
            u0 = __ldcs(rowH + lane);
            if (g2) u1 = __ldcs(rowH + lane + 32);
        }
        #pragma unroll 1
        while (i < n) {
            const int inx = i + 32;
            uint4 n0 = uz, n1 = uz;
            if (inx < n) {
                const uint4* __restrict__ rowN = (const uint4*)(H + (size_t)inx * (NDIM/2));
                n0 = __ldcs(rowN + lane);
                if (g2) n1 = __ldcs(rowN + lane + 32);
            }

            float4 c0 = c4s[lane * 2],      c1 = c4s[lane * 2 + 1];
            float4 c2 = c4s[64 + lane * 2], c3 = c4s[64 + lane * 2 + 1];
            float2 f0 = h2f(u0.x), f1 = h2f(u0.y), f2 = h2f(u0.z), f3 = h2f(u0.w);
            float2 f4 = h2f(u1.x), f5 = h2f(u1.y), f6 = h2f(u1.z), f7 = h2f(u1.w);
            float d0 = 0.f, d1 = 0.f, d2 = 0.f, d3 = 0.f;
            d0 = fmaf(f0.x, c0.x, d0); d1 = fmaf(f0.y, c0.y, d1);
            d2 = fmaf(f1.x, c0.z, d2); d3 = fmaf(f1.y, c0.w, d3);
            d0 = fmaf(f2.x, c1.x, d0); d1 = fmaf(f2.y, c1.y, d1);
            d2 = fmaf(f3.x, c1.z, d2); d3 = fmaf(f3.y, c1.w, d3);
            d0 = fmaf(f4.x, c2.x, d0); d1 = fmaf(f4.y, c2.y, d1);
            d2 = fmaf(f5.x, c2.z, d2); d3 = fmaf(f5.y, c2.w, d3);
            d0 = fmaf(f6.x, c3.x, d0); d1 = fmaf(f6.y, c3.y, d1);
            d2 = fmaf(f7.x, c3.z, d2); d3 = fmaf(f7.y, c3.w, d3);
            float t = (d0 + d1) + (d2 + d3);
            #pragma unroll
            for (int o = 16; o; o >>= 1) t += __shfl_xor_sync(0xffffffffu, t, o);
            const float ri = __fdividef(1.0f, t + eps_c);

            float4* __restrict__ orow = (float4*)(O + (size_t)i * NDIM);
            float4 w;
            w.x = (f0.x + EPS) * ri * c0.x; w.y = (f0.y + EPS) * ri * c0.y;
            w.z = (f1.x + EPS) * ri * c0.z; w.w = (f1.y + EPS) * ri * c0.w;
            __stcs(orow + lane * 2, w);
            w.x = (f2.x + EPS) * ri * c1.x; w.y = (f2.y + EPS) * ri * c1.y;
            w.z = (f3.x + EPS) * ri * c1.z; w.w = (f3.y + EPS) * ri * c1.w;
            __stcs(orow + lane * 2 + 1, w);
            w.x = (f4.x + EPS) * ri * c2.x; w.y = (f4.y + EPS) * ri * c2.y;
            w.z = (f5.x + EPS) * ri * c2.z; w.w = (f5.y + EPS) * ri * c2.w;
            __stcs(orow + 64 + lane * 2, w);
            w.x = (f6.x + EPS) * ri * c3.x; w.y = (f6.y + EPS) * ri * c3.y;
            w.z = (f7.x + EPS) * ri * c3.z; w.w = (f7.y + EPS) * ri * c3.w;
            __stcs(orow + 64 + lane * 2 + 1, w);

            u0 = n0; u1 = n1; i = inx;
        }
        // zero-fill rows i >= n
        float4* __restrict__ O4 = (float4*)O;
        const float4 z = z4f();
        for (int idx = n * 128 + tid; idx < NDIM * 128; idx += 1024)
            __stcs(O4 + idx, z);
    }
}

extern "C" void kernel_launch(void* const* d_in, const int* in_sizes, int n_in,
                              void* d_out, int out_size) {
    const float* s     = (const float*)d_in[0];
    const int*   nrows = (const int*)d_in[1];
    float*       out   = (float*)d_out;
    const int B = in_sizes[1];
    const int shbytes = 32 * NDIM * sizeof(float);   // 64 KB dynamic
    static bool attr_set = false;
    if (!attr_set) {
        cudaFuncSetAttribute(sinkhorn_kernel,
                             cudaFuncAttributeMaxDynamicSharedMemorySize, shbytes);
        attr_set = true;
    }
    sinkhorn_kernel<<<B, 1024, shbytes>>>(s, nrows, out);
}

// round 14
// speedup vs baseline: 1.2195x; 1.1925x over previous
#include <cuda_runtime.h>
#include <cuda_fp16.h>

#define EPS 1e-4f
#define NDIM 512
#define H2S 131072   // half2 per sample

__device__ __half2 g_half[128 * (size_t)H2S];   // 64 MB fp16 working copy (zero-init)

__device__ __forceinline__ float4 z4f() { return make_float4(0.f, 0.f, 0.f, 0.f); }
__device__ __forceinline__ float2 h2f(unsigned u) {
    __half2 h = *reinterpret_cast<__half2*>(&u);
    return __half22float2(h);
}
__device__ __forceinline__ float2 pack_h4(float4 v) {
    __half2 h0 = __floats2half2_rn(v.x, v.y);
    __half2 h1 = __floats2half2_rn(v.z, v.w);
    float2 r;
    r.x = __uint_as_float(*reinterpret_cast<unsigned*>(&h0));
    r.y = __uint_as_float(*reinterpret_cast<unsigned*>(&h1));
    return r;
}
// dot of one fp16 row (u0: cols 8L..8L+7, u1: cols 256+8L..+7) with c in regs
__device__ __forceinline__ float dot_row(uint4 u0, uint4 u1,
                                         float4 c0, float4 c1,
                                         float4 c2, float4 c3) {
    float2 f0 = h2f(u0.x), f1 = h2f(u0.y), f2 = h2f(u0.z), f3 = h2f(u0.w);
    float2 f4 = h2f(u1.x), f5 = h2f(u1.y), f6 = h2f(u1.z), f7 = h2f(u1.w);
    float d0 = 0.f, d1 = 0.f, d2 = 0.f, d3 = 0.f;
    d0 = fmaf(f0.x, c0.x, d0); d1 = fmaf(f0.y, c0.y, d1);
    d2 = fmaf(f1.x, c0.z, d2); d3 = fmaf(f1.y, c0.w, d3);
    d0 = fmaf(f2.x, c1.x, d0); d1 = fmaf(f2.y, c1.y, d1);
    d2 = fmaf(f3.x, c1.z, d2); d3 = fmaf(f3.y, c1.w, d3);
    d0 = fmaf(f4.x, c2.x, d0); d1 = fmaf(f4.y, c2.y, d1);
    d2 = fmaf(f5.x, c2.z, d2); d3 = fmaf(f5.y, c2.w, d3);
    d0 = fmaf(f6.x, c3.x, d0); d1 = fmaf(f6.y, c3.y, d1);
    d2 = fmaf(f7.x, c3.z, d2); d3 = fmaf(f7.y, c3.w, d3);
    return (d0 + d1) + (d2 + d3);
}
__device__ __forceinline__ void acc_row(float4& a0, float4& a1, float4& a2, float4& a3,
                                        uint4 u0, uint4 u1, float ri) {
    float2 f0 = h2f(u0.x), f1 = h2f(u0.y), f2 = h2f(u0.z), f3 = h2f(u0.w);
    a0.x = fmaf(ri, f0.x, a0.x); a0.y = fmaf(ri, f0.y, a0.y);
    a0.z = fmaf(ri, f1.x, a0.z); a0.w = fmaf(ri, f1.y, a0.w);
    a1.x = fmaf(ri, f2.x, a1.x); a1.y = fmaf(ri, f2.y, a1.y);
    a1.z = fmaf(ri, f3.x, a1.z); a1.w = fmaf(ri, f3.y, a1.w);
    float2 f4 = h2f(u1.x), f5 = h2f(u1.y), f6 = h2f(u1.z), f7 = h2f(u1.w);
    a2.x = fmaf(ri, f4.x, a2.x); a2.y = fmaf(ri, f4.y, a2.y);
    a2.z = fmaf(ri, f5.x, a2.z); a2.w = fmaf(ri, f5.y, a2.w);
    a3.x = fmaf(ri, f6.x, a3.x); a3.y = fmaf(ri, f6.y, a3.y);
    a3.z = fmaf(ri, f7.x, a3.z); a3.w = fmaf(ri, f7.y, a3.w);
}

__global__ __launch_bounds__(512, 1)
void sinkhorn_kernel(const float* __restrict__ s,
                     const int* __restrict__ nrows,
                     float* __restrict__ out) {
    extern __shared__ __align__(16) float red[];        // 16*512 floats = 32 KB
    __shared__ __align__(16) float c_sh[NDIM];
    __shared__ float ssumA[16];
    __shared__ float ssumB[16];

    const int b    = blockIdx.x;
    const int tid  = threadIdx.x;
    const int lane = tid & 31;
    const int wid  = tid >> 5;                           // 0..15
    const int n    = nrows[b];
    const bool g2  = (n > 256);
    const float* __restrict__ S = s   + (size_t)b * (NDIM * NDIM);
    float* __restrict__       O = out + (size_t)b * (NDIM * NDIM);
    __half2* __restrict__     H = g_half + (size_t)b * H2S;
    const float4* __restrict__ c4s = (const float4*)c_sh;

    // ===== pass 0: column sums (r = 1) + fp16 conversion, MLP-8 load pipeline ===
    {
        const int j4    = (tid & 127) << 2;
        const int jh    = j4 >> 1;
        const int slice = tid >> 7;                      // 0..3
        float4 a0 = z4f(), a1 = z4f(), a2 = z4f(), a3 = z4f();
        if (j4 < n) {
            int i = slice;
            for (; i + 28 < n; i += 32) {
                float4 v0 = __ldcs((const float4*)(S + (size_t)(i)      * NDIM + j4));
                float4 v1 = __ldcs((const float4*)(S + (size_t)(i + 4)  * NDIM + j4));
                float4 v2 = __ldcs((const float4*)(S + (size_t)(i + 8)  * NDIM + j4));
                float4 v3 = __ldcs((const float4*)(S + (size_t)(i + 12) * NDIM + j4));
                float4 v4 = __ldcs((const float4*)(S + (size_t)(i + 16) * NDIM + j4));
                float4 v5 = __ldcs((const float4*)(S + (size_t)(i + 20) * NDIM + j4));
                float4 v6 = __ldcs((const float4*)(S + (size_t)(i + 24) * NDIM + j4));
                float4 v7 = __ldcs((const float4*)(S + (size_t)(i + 28) * NDIM + j4));
                a0.x += v0.x + v4.x; a0.y += v0.y + v4.y;
                a0.z += v0.z + v4.z; a0.w += v0.w + v4.w;
                a1.x += v1.x + v5.x; a1.y += v1.y + v5.y;
                a1.z += v1.z + v5.z; a1.w += v1.w + v5.w;
                a2.x += v2.x + v6.x; a2.y += v2.y + v6.y;
                a2.z += v2.z + v6.z; a2.w += v2.w + v6.w;
                a3.x += v3.x + v7.x; a3.y += v3.y + v7.y;
                a3.z += v3.z + v7.z; a3.w += v3.w + v7.w;
                *(float2*)(H + (size_t)(i)      * (NDIM/2) + jh) = pack_h4(v0);
                *(float2*)(H + (size_t)(i + 4)  * (NDIM/2) + jh) = pack_h4(v1);
                *(float2*)(H + (size_t)(i + 8)  * (NDIM/2) + jh) = pack_h4(v2);
                *(float2*)(H + (size_t)(i + 12) * (NDIM/2) + jh) = pack_h4(v3);
                *(float2*)(H + (size_t)(i + 16) * (NDIM/2) + jh) = pack_h4(v4);
                *(float2*)(H + (size_t)(i + 20) * (NDIM/2) + jh) = pack_h4(v5);
                *(float2*)(H + (size_t)(i + 24) * (NDIM/2) + jh) = pack_h4(v6);
                *(float2*)(H + (size_t)(i + 28) * (NDIM/2) + jh) = pack_h4(v7);
            }
            for (; i < n; i += 4) {
                float4 v0 = __ldcs((const float4*)(S + (size_t)i * NDIM + j4));
                a0.x += v0.x; a0.y += v0.y; a0.z += v0.z; a0.w += v0.w;
                *(float2*)(H + (size_t)i * (NDIM/2) + jh) = pack_h4(v0);
            }
            a0.x += a1.x + a2.x + a3.x; a0.y += a1.y + a2.y + a3.y;
            a0.z += a1.z + a2.z + a3.z; a0.w += a1.w + a2.w + a3.w;
        }
        *(float4*)(red + slice * NDIM + j4) = a0;
        __syncthreads();

        float cv = 0.0f;
        {
            float cs = red[tid] + red[NDIM + tid] + red[2 * NDIM + tid] + red[3 * NDIM + tid];
            if (tid < n) cv = 1.0f / (cs + EPS * (float)n);
            c_sh[tid] = cv;                              // 512 threads = 512 cols
        }
        float v = cv;
        #pragma unroll
        for (int o = 16; o; o >>= 1) v += __shfl_xor_sync(0xffffffffu, v, o);
        if (lane == 0) ssumB[wid] = v;
        __syncthreads();
    }
    float sum_c = 0.0f;
    #pragma unroll
    for (int k = 0; k < 16; ++k) sum_c += ssumB[k];

    // === 4 fused passes: row(2f+1)+col(2f+2); 2-row batch + 2-row lookahead =====
    #pragma unroll 1
    for (int f = 0; f < 4; ++f) {
        const float eps_c = EPS * sum_c;
        float4 acc0 = z4f(), acc1 = z4f(), acc2 = z4f(), acc3 = z4f();
        float rpart = 0.0f;
        const uint4 uz = make_uint4(0u, 0u, 0u, 0u);

        const float4 c0 = c4s[lane * 2],      c1 = c4s[lane * 2 + 1];
        const float4 c2 = c4s[64 + lane * 2], c3 = c4s[64 + lane * 2 + 1];

        int i = wid;
        uint4 uA0 = uz, uA1 = uz, uB0 = uz, uB1 = uz;
        if (i < n) {
            const uint4* __restrict__ rA = (const uint4*)(H + (size_t)i * (NDIM/2));
            uA0 = rA[lane];
            if (g2) uA1 = rA[lane + 32];
        }
        if (i + 16 < n) {
            const uint4* __restrict__ rB = (const uint4*)(H + (size_t)(i + 16) * (NDIM/2));
            uB0 = rB[lane];
            if (g2) uB1 = rB[lane + 32];
        }
        #pragma unroll 1
        while (i < n) {
            const int inx = i + 32;
            uint4 nA0 = uz, nA1 = uz, nB0 = uz, nB1 = uz;
            if (inx < n) {
                const uint4* __restrict__ rN = (const uint4*)(H + (size_t)inx * (NDIM/2));
                nA0 = rN[lane];
                if (g2) nA1 = rN[lane + 32];
            }
            if (inx + 16 < n) {
                const uint4* __restrict__ rN = (const uint4*)(H + (size_t)(inx + 16) * (NDIM/2));
                nB0 = rN[lane];
                if (g2) nB1 = rN[lane + 32];
            }

            float tA = dot_row(uA0, uA1, c0, c1, c2, c3);
            float tB = dot_row(uB0, uB1, c0, c1, c2, c3);
            #pragma unroll
            for (int o = 16; o; o >>= 1) {
                tA += __shfl_xor_sync(0xffffffffu, tA, o);
                tB += __shfl_xor_sync(0xffffffffu, tB, o);
            }
            const float riA = 1.0f / (tA + eps_c);
            const float riB = 1.0f / (tB + eps_c);
            rpart += riA;
            acc_row(acc0, acc1, acc2, acc3, uA0, uA1, riA);
            if (i + 16 < n) {                // second row real?
                rpart += riB;
                acc_row(acc0, acc1, acc2, acc3, uB0, uB1, riB);
            }
            uA0 = nA0; uA1 = nA1; uB0 = nB0; uB1 = nB1; i = inx;
        }

        float4* __restrict__ rw = (float4*)(red + wid * NDIM);
        rw[lane * 2]          = acc0;
        rw[lane * 2 + 1]      = acc1;
        rw[64 + lane * 2]     = acc2;
        rw[64 + lane * 2 + 1] = acc3;
        if (lane == 0) ssumA[wid] = rpart;   // warp-uniform
        __syncthreads();

        float sum_r = 0.0f;
        #pragma unroll
        for (int k = 0; k < 16; ++k) sum_r += ssumA[k];

        float cv = 0.0f;
        {
            float cs = 0.0f;
            #pragma unroll
            for (int w = 0; w < 16; ++w) cs += red[w * NDIM + tid];
            if (tid < n) cv = 1.0f / (cs + EPS * sum_r);
            c_sh[tid] = cv;
        }
        float v = cv;
        #pragma unroll
        for (int o = 16; o; o >>= 1) v += __shfl_xor_sync(0xffffffffu, v, o);
        if (lane == 0) ssumB[wid] = v;
        __syncthreads();
        sum_c = 0.0f;
        #pragma unroll
        for (int k = 0; k < 16; ++k) sum_c += ssumB[k];
    }

    // === final pass: row step (iter 9) on fp16 copy, 2-row batch, fused write ===
    {
        const float eps_c = EPS * sum_c;
        const uint4 uz = make_uint4(0u, 0u, 0u, 0u);
        const float4 c0 = c4s[lane * 2],      c1 = c4s[lane * 2 + 1];
        const float4 c2 = c4s[64 + lane * 2], c3 = c4s[64 + lane * 2 + 1];

        for (int i = wid; i < n; i += 32) {
            const int i2 = i + 16;
            const uint4* __restrict__ rA = (const uint4*)(H + (size_t)i * (NDIM/2));
            uint4 uA0 = __ldcs(rA + lane);
            uint4 uA1 = uz;
            if (g2) uA1 = __ldcs(rA + lane + 32);
            uint4 uB0 = uz, uB1 = uz;
            if (i2 < n) {
                const uint4* __restrict__ rB = (const uint4*)(H + (size_t)i2 * (NDIM/2));
                uB0 = __ldcs(rB + lane);
                if (g2) uB1 = __ldcs(rB + lane + 32);
            }

            float tA = dot_row(uA0, uA1, c0, c1, c2, c3);
            float tB = dot_row(uB0, uB1, c0, c1, c2, c3);
            #pragma unroll
            for (int o = 16; o; o >>= 1) {
                tA += __shfl_xor_sync(0xffffffffu, tA, o);
                tB += __shfl_xor_sync(0xffffffffu, tB, o);
            }
            const float riA = 1.0f / (tA + eps_c);
            const float riB = 1.0f / (tB + eps_c);

            {
                float4* __restrict__ orow = (float4*)(O + (size_t)i * NDIM);
                float2 f0 = h2f(uA0.x), f1 = h2f(uA0.y), f2 = h2f(uA0.z), f3 = h2f(uA0.w);
                float2 f4 = h2f(uA1.x), f5 = h2f(uA1.y), f6 = h2f(uA1.z), f7 = h2f(uA1.w);
                float4 w;
                w.x = (f0.x + EPS) * riA * c0.x; w.y = (f0.y + EPS) * riA * c0.y;
                w.z = (f1.x + EPS) * riA * c0.z; w.w = (f1.y + EPS) * riA * c0.w;
                __stcs(orow + lane * 2, w);
                w.x = (f2.x + EPS) * riA * c1.x; w.y = (f2.y + EPS) * riA * c1.y;
                w.z = (f3.x + EPS) * riA * c1.z; w.w = (f3.y + EPS) * riA * c1.w;
                __stcs(orow + lane * 2 + 1, w);
                w.x = (f4.x + EPS) * riA * c2.x; w.y = (f4.y + EPS) * riA * c2.y;
                w.z = (f5.x + EPS) * riA * c2.z; w.w = (f5.y + EPS) * riA * c2.w;
                __stcs(orow + 64 + lane * 2, w);
                w.x = (f6.x + EPS) * riA * c3.x; w.y = (f6.y + EPS) * riA * c3.y;
                w.z = (f7.x + EPS) * riA * c3.z; w.w = (f7.y + EPS) * riA * c3.w;
                __stcs(orow + 64 + lane * 2 + 1, w);
            }
            if (i2 < n) {
                float4* __restrict__ orow = (float4*)(O + (size_t)i2 * NDIM);
                float2 f0 = h2f(uB0.x), f1 = h2f(uB0.y), f2 = h2f(uB0.z), f3 = h2f(uB0.w);
                float2 f4 = h2f(uB1.x), f5 = h2f(uB1.y), f6 = h2f(uB1.z), f7 = h2f(uB1.w);
                float4 w;
                w.x = (f0.x + EPS) * riB * c0.x; w.y = (f0.y + EPS) * riB * c0.y;
                w.z = (f1.x + EPS) * riB * c0.z; w.w = (f1.y + EPS) * riB * c0.w;
                __stcs(orow + lane * 2, w);
                w.x = (f2.x + EPS) * riB * c1.x; w.y = (f2.y + EPS) * riB * c1.y;
                w.z = (f3.x + EPS) * riB * c1.z; w.w = (f3.y + EPS) * riB * c1.w;
                __stcs(orow + lane * 2 + 1, w);
                w.x = (f4.x + EPS) * riB * c2.x; w.y = (f4.y + EPS) * riB * c2.y;
                w.z = (f5.x + EPS) * riB * c2.z; w.w = (f5.y + EPS) * riB * c2.w;
                __stcs(orow + 64 + lane * 2, w);
                w.x = (f6.x + EPS) * riB * c3.x; w.y = (f6.y + EPS) * riB * c3.y;
                w.z = (f7.x + EPS) * riB * c3.z; w.w = (f7.y + EPS) * riB * c3.w;
                __stcs(orow + 64 + lane * 2 + 1, w);
            }
        }
        // zero-fill rows i >= n
        float4* __restrict__ O4 = (float4*)O;
        const float4 z = z4f();
        for (int idx = n * 128 + tid; idx < NDIM * 128; idx += 512)
            __stcs(O4 + idx, z);
    }
}

extern "C" void kernel_launch(void* const* d_in, const int* in_sizes, int n_in,
                              void* d_out, int out_size) {
    const float* s     = (const float*)d_in[0];
    const int*   nrows = (const int*)d_in[1];
    float*       out   = (float*)d_out;
    const int B = in_sizes[1];
    const int shbytes = 16 * NDIM * sizeof(float);   // 32 KB dynamic
    static bool attr_set = false;
    if (!attr_set) {
        cudaFuncSetAttribute(sinkhorn_kernel,
                             cudaFuncAttributeMaxDynamicSharedMemorySize, shbytes);
        attr_set = true;
    }
    sinkhorn_kernel<<<B, 512, shbytes>>>(s, nrows, out);
}